// round 3
// baseline (speedup 1.0000x reference)
#include <cuda_runtime.h>
#include <cuda_bf16.h>
#include <math.h>

#define NT 256

namespace {

constexpr int Bc  = 2;
constexpr int Hc  = 16;
constexpr int Sc  = 4096;
constexpr int DKc = 128;
constexpr int DVc = 256;
constexpr int Lc  = 64;     // chunk length
constexpr int DVB = 64;     // Dv block per CTA
constexpr int BHc = Bc * Hc;          // 32
constexpr int NCH = Sc / Lc;          // 64 chunks
constexpr int NBv = DVc / DVB;        // 4 Dv blocks

constexpr float kScale = 0.08838834764831845f;   // 128^-0.5
constexpr long long OUT_ELEMS   = (long long)BHc * Sc * DVc;     // 33554432
constexpr long long STATE_ELEMS = (long long)BHc * DKc * DVc;    // 1048576

struct Smem {
  float q[Lc][DKc];      // normalized q chunk
  float k[Lc][DKc];      // normalized k chunk
  float kt[DKc][Lc];     // k transposed (conflict-free B-operand for k^T gemms)
  float v[Lc][DVB];      // v chunk slice; becomes R = gexp*(V - K@S) in place
  float a[Lc][Lc];       // A strict-lower (solve input); reused as gated qk^T
  float t[Lc][Lc];       // T = A^-1 diag(beta)
  float c[Lc][DVB];      // correction C
  float S[DKc][DVB];     // running state slice
  float part[2][Lc][4];  // norm partial sums (0: q, 1: k)
  float ninv[2][Lc];     // 1/(||row||+eps)
  float gcum[Lc];
  float gexp[Lc];        // exp(gcum)
  float ginv[Lc];        // 1/exp(gcum)
  float beta[Lc];
};

#define LD4(dst, src) *reinterpret_cast<float4*>(dst) = *reinterpret_cast<const float4*>(src)

__device__ __forceinline__ void mm4x4(float acc[4][4], const float Af[4][4], const float Bf[4][4]) {
  #pragma unroll
  for (int r = 0; r < 4; ++r)
    #pragma unroll
    for (int kk = 0; kk < 4; ++kk)
      #pragma unroll
      for (int ss = 0; ss < 4; ++ss)
        acc[r][ss] += Af[r][kk] * Bf[kk][ss];
}

__global__ void __launch_bounds__(NT, 1) gdn_kernel(
    const float* __restrict__ gq, const float* __restrict__ gk,
    const float* __restrict__ gv, const float* __restrict__ gg,
    const float* __restrict__ gb, float* __restrict__ out,
    long long out_elems)
{
  extern __shared__ char smem_raw[];
  Smem& s = *reinterpret_cast<Smem*>(smem_raw);

  const int tid = threadIdx.x;
  const int vb  = blockIdx.x;   // Dv block
  const int bh  = blockIdx.y;   // fused batch*head

  const size_t qkbase = (size_t)bh * Sc * DKc;
  const size_t vbase  = (size_t)bh * Sc * DVc + (size_t)vb * DVB;
  const size_t gbase  = (size_t)bh * Sc;

  // zero state
  for (int i = tid; i < DKc * DVB; i += NT) (&s.S[0][0])[i] = 0.f;
  __syncthreads();

  const int ty = tid >> 4;            // 0..15
  const int tx = tid & 15;            // 0..15
  const int ldrow = (tid * 32) >> 7;  // q/k load row (0..63)
  const int ldcol = (tid * 32) & 127; // q/k load col offset

  for (int n = 0; n < NCH; ++n) {
    // ================= Phase A: load + normalize q,k; load v,g,beta ========
    const float* qg = gq + qkbase + (size_t)n * Lc * DKc + tid * 32;
    const float* kg = gk + qkbase + (size_t)n * Lc * DKc + tid * 32;
    float4 bq[8], bk[8];
    float sq = 0.f, sk = 0.f;
    #pragma unroll
    for (int u = 0; u < 8; ++u) {
      float4 x = *reinterpret_cast<const float4*>(qg + u * 4);
      float4 y = *reinterpret_cast<const float4*>(kg + u * 4);
      bq[u] = x; bk[u] = y;
      sq += x.x * x.x + x.y * x.y + x.z * x.z + x.w * x.w;
      sk += y.x * y.x + y.y * y.y + y.z * y.z + y.w * y.w;
    }
    s.part[0][ldrow][ldcol >> 5] = sq;
    s.part[1][ldrow][ldcol >> 5] = sk;
    #pragma unroll
    for (int u = 0; u < 4; ++u) {
      int f = tid * 4 + u;
      int r = f >> 4, c4 = (f & 15) * 4;
      LD4(&s.v[r][c4], gv + vbase + (size_t)(n * Lc + r) * DVc + c4);
    }
    if (tid < Lc) {
      s.gcum[tid] = gg[gbase + n * Lc + tid];
      s.beta[tid] = gb[gbase + n * Lc + tid];
    }
    __syncthreads();

    if (tid < 2 * Lc) {
      int w = tid >> 6, r = tid & 63;
      float ssum = s.part[w][r][0] + s.part[w][r][1] + s.part[w][r][2] + s.part[w][r][3];
      s.ninv[w][r] = 1.f / (sqrtf(ssum) + 1e-6f);
    }
    if (tid == 128) {  // sequential cumsum over 64 gates (cheap)
      float acc = 0.f;
      for (int i = 0; i < Lc; ++i) { acc += s.gcum[i]; s.gcum[i] = acc; }
    }
    __syncthreads();

    if (tid < Lc) {
      float e = expf(s.gcum[tid]);
      s.gexp[tid] = e;
      s.ginv[tid] = 1.f / e;
    }
    {
      float iq = s.ninv[0][ldrow], ik = s.ninv[1][ldrow];
      #pragma unroll
      for (int u = 0; u < 8; ++u) {
        float4 x = bq[u];
        x.x *= iq; x.y *= iq; x.z *= iq; x.w *= iq;
        *reinterpret_cast<float4*>(&s.q[ldrow][ldcol + u * 4]) = x;
        float4 y = bk[u];
        y.x *= ik; y.y *= ik; y.z *= ik; y.w *= ik;
        *reinterpret_cast<float4*>(&s.k[ldrow][ldcol + u * 4]) = y;
        s.kt[ldcol + u * 4 + 0][ldrow] = y.x;
        s.kt[ldcol + u * 4 + 1][ldrow] = y.y;
        s.kt[ldcol + u * 4 + 2][ldrow] = y.z;
        s.kt[ldcol + u * 4 + 3][ldrow] = y.w;
      }
    }
    __syncthreads();

    // ================= Phase B: A = strict_lower( beta_i * (k_i.k_j) * e^{gj-gi} )
    {
      const int i0 = ty * 4, j0 = tx * 4;
      float acc[4][4] = {};
      #pragma unroll 4
      for (int d = 0; d < DKc; d += 4) {
        float Af[4][4], Bf[4][4];
        #pragma unroll
        for (int r = 0; r < 4; ++r) LD4(&Af[r][0], &s.k[i0 + r][d]);
        #pragma unroll
        for (int dd = 0; dd < 4; ++dd) LD4(&Bf[dd][0], &s.kt[d + dd][j0]);
        mm4x4(acc, Af, Bf);
      }
      #pragma unroll
      for (int r = 0; r < 4; ++r) {
        int i = i0 + r;
        float bi = s.beta[i] * s.ginv[i];
        #pragma unroll
        for (int ss = 0; ss < 4; ++ss) {
          int j = j0 + ss;
          s.a[i][j] = (j < i) ? bi * acc[r][ss] * s.gexp[j] : 0.f;
        }
      }
    }
    __syncthreads();

    // ================= Phase C: R = gexp[j] * (V - K@S), in place in s.v ====
    {
      const int j0 = ty * 4, c0 = tx * 4;
      float acc[4][4] = {};
      #pragma unroll 4
      for (int d = 0; d < DKc; d += 4) {
        float Af[4][4], Bf[4][4];
        #pragma unroll
        for (int r = 0; r < 4; ++r) LD4(&Af[r][0], &s.k[j0 + r][d]);
        #pragma unroll
        for (int dd = 0; dd < 4; ++dd) LD4(&Bf[dd][0], &s.S[d + dd][c0]);
        mm4x4(acc, Af, Bf);
      }
      #pragma unroll
      for (int r = 0; r < 4; ++r) {
        float ge = s.gexp[j0 + r];
        float4 vv = *reinterpret_cast<float4*>(&s.v[j0 + r][c0]);
        vv.x = ge * (vv.x - acc[r][0]);
        vv.y = ge * (vv.y - acc[r][1]);
        vv.z = ge * (vv.z - acc[r][2]);
        vv.w = ge * (vv.w - acc[r][3]);
        *reinterpret_cast<float4*>(&s.v[j0 + r][c0]) = vv;
      }
    }
    // no explicit barrier needed: solve iteration 0 has no dependencies and
    // every solve iteration ends in __syncthreads().

    // ================= Phase D: forward substitution T = A^-1 diag(beta) ====
    for (int i = 0; i < Lc; ++i) {
      if (tid < Lc) {
        float a0 = 0.f, a1 = 0.f, a2 = 0.f, a3 = 0.f;
        int j = 0;
        for (; j + 4 <= i; j += 4) {
          a0 += s.a[i][j + 0] * s.t[j + 0][tid];
          a1 += s.a[i][j + 1] * s.t[j + 1][tid];
          a2 += s.a[i][j + 2] * s.t[j + 2][tid];
          a3 += s.a[i][j + 3] * s.t[j + 3][tid];
        }
        for (; j < i; ++j) a0 += s.a[i][j] * s.t[j][tid];
        float val = ((tid == i) ? s.beta[i] : 0.f) - (a0 + a1 + a2 + a3);
        s.t[i][tid] = val;
      }
      __syncthreads();
    }

    // ================= Phase E: C = T @ R ; qkg into s.a ====================
    {
      const int i0 = ty * 4, c0 = tx * 4;
      float acc[4][4] = {};
      #pragma unroll 4
      for (int j = 0; j < Lc; j += 4) {
        float Af[4][4], Bf[4][4];
        #pragma unroll
        for (int r = 0; r < 4; ++r) LD4(&Af[r][0], &s.t[i0 + r][j]);
        #pragma unroll
        for (int jj = 0; jj < 4; ++jj) LD4(&Bf[jj][0], &s.v[j + jj][c0]);
        mm4x4(acc, Af, Bf);
      }
      #pragma unroll
      for (int r = 0; r < 4; ++r) {
        *reinterpret_cast<float4*>(&s.c[i0 + r][c0]) =
            make_float4(acc[r][0], acc[r][1], acc[r][2], acc[r][3]);
      }

      // qkg[i][j] = (j<=i) ? (q_i.k_j) * e^{gj-gi} : 0
      const int j0 = tx * 4;
      float acc2[4][4] = {};
      #pragma unroll 4
      for (int d = 0; d < DKc; d += 4) {
        float Af[4][4], Bf[4][4];
        #pragma unroll
        for (int r = 0; r < 4; ++r) LD4(&Af[r][0], &s.q[i0 + r][d]);
        #pragma unroll
        for (int dd = 0; dd < 4; ++dd) LD4(&Bf[dd][0], &s.kt[d + dd][j0]);
        mm4x4(acc2, Af, Bf);
      }
      #pragma unroll
      for (int r = 0; r < 4; ++r) {
        int i = i0 + r;
        float gi = s.ginv[i];
        #pragma unroll
        for (int ss = 0; ss < 4; ++ss) {
          int j = j0 + ss;
          s.a[i][j] = (j <= i) ? acc2[r][ss] * s.gexp[j] * gi : 0.f;
        }
      }
    }
    __syncthreads();

    // ================= Phase F: O = SCALE*(gexp[i]*(q@S) + qkg@C), store ====
    {
      const int i0 = ty * 4, c0 = tx * 4;
      float accI[4][4] = {};
      #pragma unroll 4
      for (int d = 0; d < DKc; d += 4) {
        float Af[4][4], Bf[4][4];
        #pragma unroll
        for (int r = 0; r < 4; ++r) LD4(&Af[r][0], &s.q[i0 + r][d]);
        #pragma unroll
        for (int dd = 0; dd < 4; ++dd) LD4(&Bf[dd][0], &s.S[d + dd][c0]);
        mm4x4(accI, Af, Bf);
      }
      float accA[4][4] = {};
      #pragma unroll 4
      for (int j = 0; j < Lc; j += 4) {
        float Af[4][4], Bf[4][4];
        #pragma unroll
        for (int r = 0; r < 4; ++r) LD4(&Af[r][0], &s.a[i0 + r][j]);
        #pragma unroll
        for (int jj = 0; jj < 4; ++jj) LD4(&Bf[jj][0], &s.c[j + jj][c0]);
        mm4x4(accA, Af, Bf);
      }
      const size_t obase = ((size_t)bh * Sc + (size_t)n * Lc) * DVc + (size_t)vb * DVB;
      #pragma unroll
      for (int r = 0; r < 4; ++r) {
        int i = i0 + r;
        float ge = s.gexp[i];
        float4 o;
        o.x = kScale * (ge * accI[r][0] + accA[r][0]);
        o.y = kScale * (ge * accI[r][1] + accA[r][1]);
        o.z = kScale * (ge * accI[r][2] + accA[r][2]);
        o.w = kScale * (ge * accI[r][3] + accA[r][3]);
        *reinterpret_cast<float4*>(&out[obase + (size_t)i * DVc + c0]) = o;
      }
    }
    __syncthreads();

    // ================= Phase G: S = S*exp(g_total) + (gexp*k)^T @ C =========
    {
      const int d0 = (tid >> 4) * 8, c0 = (tid & 15) * 4;
      const float egt = s.gexp[Lc - 1];
      float acc[8][4] = {};
      #pragma unroll 4
      for (int i = 0; i < Lc; ++i) {
        float ge = s.gexp[i];
        float4 cv = *reinterpret_cast<const float4*>(&s.c[i][c0]);
        cv.x *= ge; cv.y *= ge; cv.z *= ge; cv.w *= ge;
        float kf[8];
        LD4(&kf[0], &s.k[i][d0]);
        LD4(&kf[4], &s.k[i][d0 + 4]);
        #pragma unroll
        for (int r = 0; r < 8; ++r) {
          acc[r][0] += kf[r] * cv.x;
          acc[r][1] += kf[r] * cv.y;
          acc[r][2] += kf[r] * cv.z;
          acc[r][3] += kf[r] * cv.w;
        }
      }
      #pragma unroll
      for (int r = 0; r < 8; ++r) {
        float4 sv = *reinterpret_cast<float4*>(&s.S[d0 + r][c0]);
        sv.x = sv.x * egt + acc[r][0];
        sv.y = sv.y * egt + acc[r][1];
        sv.z = sv.z * egt + acc[r][2];
        sv.w = sv.w * egt + acc[r][3];
        *reinterpret_cast<float4*>(&s.S[d0 + r][c0]) = sv;
      }
    }
    __syncthreads();
  }  // chunk loop

  // Final state (second tuple element), if the output buffer includes it.
  if (out_elems >= OUT_ELEMS + STATE_ELEMS) {
    float* st = out + OUT_ELEMS + (size_t)bh * DKc * DVc + (size_t)vb * DVB;
    for (int f = tid; f < DKc * DVB / 4; f += NT) {
      int d = f >> 4, c4 = (f & 15) * 4;
      *reinterpret_cast<float4*>(&st[(size_t)d * DVc + c4]) =
          *reinterpret_cast<const float4*>(&s.S[d][c4]);
    }
  }
}

}  // namespace

extern "C" void kernel_launch(void* const* d_in, const int* in_sizes, int n_in,
                              void* d_out, int out_size) {
  (void)in_sizes; (void)n_in;
  const float* q  = (const float*)d_in[0];
  const float* k  = (const float*)d_in[1];
  const float* v  = (const float*)d_in[2];
  const float* g  = (const float*)d_in[3];
  const float* be = (const float*)d_in[4];

  cudaFuncSetAttribute(gdn_kernel, cudaFuncAttributeMaxDynamicSharedMemorySize,
                       (int)sizeof(Smem));

  dim3 grid(NBv, BHc);
  gdn_kernel<<<grid, NT, sizeof(Smem)>>>(q, k, v, g, be, (float*)d_out,
                                         (long long)out_size);
}

// round 4
// speedup vs baseline: 1.5307x; 1.5307x over previous
#include <cuda_runtime.h>
#include <cuda_bf16.h>
#include <math.h>

#define NT 256

namespace {

constexpr int Bc  = 2;
constexpr int Hc  = 16;
constexpr int Sc  = 4096;
constexpr int DKc = 128;
constexpr int DVc = 256;
constexpr int Lc  = 64;     // chunk length
constexpr int DVB = 64;     // Dv block per CTA
constexpr int BHc = Bc * Hc;          // 32
constexpr int NCH = Sc / Lc;          // 64 chunks
constexpr int NBv = DVc / DVB;        // 4 Dv blocks

constexpr float kScale = 0.08838834764831845f;   // 128^-0.5
constexpr long long OUT_ELEMS   = (long long)BHc * Sc * DVc;     // 33554432
constexpr long long STATE_ELEMS = (long long)BHc * DKc * DVc;    // 1048576

typedef unsigned long long u64;

struct Smem {
  float q[Lc][DKc];      // normalized q chunk
  float k[Lc][DKc];      // normalized k chunk
  float kt[DKc][Lc];     // k transposed
  float v[Lc][DVB];      // v slice; becomes R = gexp*(V - K@S) in place
  float a[Lc][Lc];       // A strict-lower gated (solve input)
  float w[Lc][Lc];       // qkg (gated causal q k^T)
  float t[Lc][Lc];       // T = A^-1 diag(beta)
  float c[Lc][DVB];      // solve scratch P, then correction C
  float S[DKc][DVB];     // running state slice
  float part[2][Lc][4];  // norm partial sums
  float ninv[2][Lc];
  float gcum[Lc];
  float gexp[Lc];
  float ginv[Lc];
  float beta[Lc];
};

#define LD4(dst, src) *reinterpret_cast<float4*>(dst) = *reinterpret_cast<const float4*>(src)

// ---- packed f32x2 helpers (Blackwell FFMA2 path, PTX-only) ----------------
__device__ __forceinline__ u64 pk2(float a) {
  u64 r; unsigned int ai = __float_as_uint(a);
  asm("mov.b64 %0, {%1, %1};" : "=l"(r) : "r"(ai));
  return r;
}
__device__ __forceinline__ u64 ffma2(u64 a, u64 b, u64 c) {
  u64 d;
  asm("fma.rn.f32x2 %0, %1, %2, %3;" : "=l"(d) : "l"(a), "l"(b), "l"(c));
  return d;
}
__device__ __forceinline__ u64 fmul2(u64 a, u64 b) {
  u64 d;
  asm("mul.rn.f32x2 %0, %1, %2;" : "=l"(d) : "l"(a), "l"(b));
  return d;
}
__device__ __forceinline__ float2 upk(u64 a) {
  unsigned int lo, hi;
  asm("mov.b64 {%0, %1}, %2;" : "=r"(lo), "=r"(hi) : "l"(a));
  return make_float2(__uint_as_float(lo), __uint_as_float(hi));
}

// acc[4 rows][2 col-pairs] += Af[4][4] (scalar) * Bv[4][2] (packed pairs)
__device__ __forceinline__ void mm4x4p(u64 acc[4][2], const float Af[4][4],
                                       const u64 Bv[4][2]) {
  #pragma unroll
  for (int r = 0; r < 4; ++r)
    #pragma unroll
    for (int kk = 0; kk < 4; ++kk) {
      u64 pa = pk2(Af[r][kk]);
      acc[r][0] = ffma2(pa, Bv[kk][0], acc[r][0]);
      acc[r][1] = ffma2(pa, Bv[kk][1], acc[r][1]);
    }
}

__device__ __forceinline__ void ldBv(u64 Bv2[2], const float* p) {
  ulonglong2 b = *reinterpret_cast<const ulonglong2*>(p);
  Bv2[0] = b.x; Bv2[1] = b.y;
}

__global__ void __launch_bounds__(NT, 1) gdn_kernel(
    const float* __restrict__ gq, const float* __restrict__ gk,
    const float* __restrict__ gv, const float* __restrict__ gg,
    const float* __restrict__ gb, float* __restrict__ out,
    long long out_elems)
{
  extern __shared__ char smem_raw[];
  Smem& s = *reinterpret_cast<Smem*>(smem_raw);

  const int tid = threadIdx.x;
  const int vb  = blockIdx.x;   // Dv block
  const int bh  = blockIdx.y;   // fused batch*head

  const size_t qkbase = (size_t)bh * Sc * DKc;
  const size_t vbase  = (size_t)bh * Sc * DVc + (size_t)vb * DVB;
  const size_t gbase  = (size_t)bh * Sc;

  for (int i = tid; i < DKc * DVB; i += NT) (&s.S[0][0])[i] = 0.f;
  __syncthreads();

  const int ty = tid >> 4;            // 0..15
  const int tx = tid & 15;            // 0..15
  const int ldrow = (tid * 32) >> 7;  // q/k load row (0..63)
  const int ldcol = (tid * 32) & 127; // q/k load col offset

  for (int n = 0; n < NCH; ++n) {
    // ================= Phase A: load + normalize q,k; load v,g,beta ========
    const float* qg = gq + qkbase + (size_t)n * Lc * DKc + tid * 32;
    const float* kg = gk + qkbase + (size_t)n * Lc * DKc + tid * 32;
    float4 bq[8], bk[8];
    float sq = 0.f, sk = 0.f;
    #pragma unroll
    for (int u = 0; u < 8; ++u) {
      float4 x = *reinterpret_cast<const float4*>(qg + u * 4);
      float4 y = *reinterpret_cast<const float4*>(kg + u * 4);
      bq[u] = x; bk[u] = y;
      sq += x.x * x.x + x.y * x.y + x.z * x.z + x.w * x.w;
      sk += y.x * y.x + y.y * y.y + y.z * y.z + y.w * y.w;
    }
    s.part[0][ldrow][ldcol >> 5] = sq;
    s.part[1][ldrow][ldcol >> 5] = sk;
    #pragma unroll
    for (int u = 0; u < 4; ++u) {
      int f = tid * 4 + u;
      int r = f >> 4, c4 = (f & 15) * 4;
      LD4(&s.v[r][c4], gv + vbase + (size_t)(n * Lc + r) * DVc + c4);
    }
    if (tid < Lc) {
      s.gcum[tid] = gg[gbase + n * Lc + tid];
      s.beta[tid] = gb[gbase + n * Lc + tid];
    }
    __syncthreads();

    if (tid < 2 * Lc) {
      int w = tid >> 6, r = tid & 63;
      float ssum = s.part[w][r][0] + s.part[w][r][1] + s.part[w][r][2] + s.part[w][r][3];
      s.ninv[w][r] = 1.f / (sqrtf(ssum) + 1e-6f);
    }
    if (tid == 128) {  // sequential cumsum over 64 gates (cheap)
      float acc = 0.f;
      for (int i = 0; i < Lc; ++i) { acc += s.gcum[i]; s.gcum[i] = acc; }
    }
    __syncthreads();

    if (tid < Lc) {
      float e = expf(s.gcum[tid]);
      s.gexp[tid] = e;
      s.ginv[tid] = 1.f / e;
    }
    {
      float iq = s.ninv[0][ldrow], ik = s.ninv[1][ldrow];
      #pragma unroll
      for (int u = 0; u < 8; ++u) {
        float4 x = bq[u];
        x.x *= iq; x.y *= iq; x.z *= iq; x.w *= iq;
        *reinterpret_cast<float4*>(&s.q[ldrow][ldcol + u * 4]) = x;
        float4 y = bk[u];
        y.x *= ik; y.y *= ik; y.z *= ik; y.w *= ik;
        *reinterpret_cast<float4*>(&s.k[ldrow][ldcol + u * 4]) = y;
        s.kt[ldcol + u * 4 + 0][ldrow] = y.x;
        s.kt[ldcol + u * 4 + 1][ldrow] = y.y;
        s.kt[ldcol + u * 4 + 2][ldrow] = y.z;
        s.kt[ldcol + u * 4 + 3][ldrow] = y.w;
      }
    }
    __syncthreads();

    // ===== Phase B (fused): A = k k^T and qkg = q k^T, sharing kt loads ====
    {
      const int i0 = ty * 4, j0 = tx * 4;
      u64 aA[4][2] = {}, aQ[4][2] = {};
      #pragma unroll 2
      for (int d = 0; d < DKc; d += 4) {
        u64 Bv[4][2];
        #pragma unroll
        for (int dd = 0; dd < 4; ++dd) ldBv(Bv[dd], &s.kt[d + dd][j0]);
        float Af[4][4];
        #pragma unroll
        for (int r = 0; r < 4; ++r) LD4(&Af[r][0], &s.k[i0 + r][d]);
        mm4x4p(aA, Af, Bv);
        #pragma unroll
        for (int r = 0; r < 4; ++r) LD4(&Af[r][0], &s.q[i0 + r][d]);
        mm4x4p(aQ, Af, Bv);
      }
      #pragma unroll
      for (int r = 0; r < 4; ++r) {
        int i = i0 + r;
        float bi = s.beta[i] * s.ginv[i];
        float gi = s.ginv[i];
        #pragma unroll
        for (int p = 0; p < 2; ++p) {
          float2 fa = upk(aA[r][p]);
          float2 fq = upk(aQ[r][p]);
          int j = j0 + 2 * p;
          s.a[i][j]     = (j     < i) ? bi * fa.x * s.gexp[j]     : 0.f;
          s.a[i][j + 1] = (j + 1 < i) ? bi * fa.y * s.gexp[j + 1] : 0.f;
          s.w[i][j]     = (j     <= i) ? fq.x * s.gexp[j]     * gi : 0.f;
          s.w[i][j + 1] = (j + 1 <= i) ? fq.y * s.gexp[j + 1] * gi : 0.f;
        }
      }
    }
    // no barrier: next phase touches only S/q/k/v; barrier before solve below

    // ===== Phase C (fused): R = gexp*(V - K@S) in s.v ; OI = Q@S in regs ===
    u64 accI[4][2] = {};   // persistent packed O_inter tile, consumed in F
    {
      const int r0 = ty * 4, c0 = tx * 4;
      u64 aK[4][2] = {};
      #pragma unroll 2
      for (int d = 0; d < DKc; d += 4) {
        u64 Bv[4][2];
        #pragma unroll
        for (int dd = 0; dd < 4; ++dd) ldBv(Bv[dd], &s.S[d + dd][c0]);
        float Af[4][4];
        #pragma unroll
        for (int r = 0; r < 4; ++r) LD4(&Af[r][0], &s.k[r0 + r][d]);
        mm4x4p(aK, Af, Bv);
        #pragma unroll
        for (int r = 0; r < 4; ++r) LD4(&Af[r][0], &s.q[r0 + r][d]);
        mm4x4p(accI, Af, Bv);
      }
      #pragma unroll
      for (int r = 0; r < 4; ++r) {
        float ge = s.gexp[r0 + r];
        float2 f0 = upk(aK[r][0]), f1 = upk(aK[r][1]);
        float4 vv = *reinterpret_cast<float4*>(&s.v[r0 + r][c0]);
        vv.x = ge * (vv.x - f0.x);
        vv.y = ge * (vv.y - f0.y);
        vv.z = ge * (vv.z - f1.x);
        vv.w = ge * (vv.w - f1.y);
        *reinterpret_cast<float4*>(&s.v[r0 + r][c0]) = vv;
      }
    }
    __syncthreads();   // s.a/s.w complete, s.v(R) complete

    // ===== Phase D: blocked forward substitution, T = A^-1 diag(beta) ======
    // Block 0: rows 0..31 (column-parallel, barrier-free, register-resident)
    if (tid < Lc) {
      float tc[32];
      #pragma unroll
      for (int i = 0; i < 32; ++i) {
        float val = (tid == i) ? s.beta[i] : 0.f;
        #pragma unroll
        for (int j = 0; j < i; ++j) val -= s.a[i][j] * tc[j];
        tc[i] = val;
        s.t[i][tid] = val;
      }
    }
    __syncthreads();
    // Off-diagonal: P[32][64] = A[32:64][0:32] @ T[0:32][:]  (all 256 threads)
    {
      const int rp0 = (tid >> 5) * 4;   // 0..28
      const int cp0 = (tid & 31) * 2;   // 0..62
      float accP[4][2] = {};
      #pragma unroll
      for (int j = 0; j < 32; j += 4) {
        float Bf[4][2];
        #pragma unroll
        for (int jj = 0; jj < 4; ++jj) {
          float2 t2 = *reinterpret_cast<const float2*>(&s.t[j + jj][cp0]);
          Bf[jj][0] = t2.x; Bf[jj][1] = t2.y;
        }
        #pragma unroll
        for (int r = 0; r < 4; ++r) {
          float4 av = *reinterpret_cast<const float4*>(&s.a[32 + rp0 + r][j]);
          accP[r][0] += av.x * Bf[0][0] + av.y * Bf[1][0] + av.z * Bf[2][0] + av.w * Bf[3][0];
          accP[r][1] += av.x * Bf[0][1] + av.y * Bf[1][1] + av.z * Bf[2][1] + av.w * Bf[3][1];
        }
      }
      #pragma unroll
      for (int r = 0; r < 4; ++r) {
        s.c[rp0 + r][cp0]     = accP[r][0];
        s.c[rp0 + r][cp0 + 1] = accP[r][1];
      }
    }
    __syncthreads();
    // Block 1: rows 32..63
    if (tid < Lc) {
      float tc[32];
      #pragma unroll
      for (int i = 0; i < 32; ++i) {
        int gi = 32 + i;
        float val = ((tid == gi) ? s.beta[gi] : 0.f) - s.c[i][tid];
        #pragma unroll
        for (int j = 0; j < i; ++j) val -= s.a[gi][32 + j] * tc[j];
        tc[i] = val;
        s.t[gi][tid] = val;
      }
    }
    __syncthreads();

    // ===== Phase E: C = T @ R ==============================================
    {
      const int i0 = ty * 4, c0 = tx * 4;
      u64 aC[4][2] = {};
      #pragma unroll 4
      for (int j = 0; j < Lc; j += 4) {
        u64 Bv[4][2];
        #pragma unroll
        for (int jj = 0; jj < 4; ++jj) ldBv(Bv[jj], &s.v[j + jj][c0]);
        float Af[4][4];
        #pragma unroll
        for (int r = 0; r < 4; ++r) LD4(&Af[r][0], &s.t[i0 + r][j]);
        mm4x4p(aC, Af, Bv);
      }
      #pragma unroll
      for (int r = 0; r < 4; ++r) {
        float2 f0 = upk(aC[r][0]), f1 = upk(aC[r][1]);
        *reinterpret_cast<float4*>(&s.c[i0 + r][c0]) =
            make_float4(f0.x, f0.y, f1.x, f1.y);
      }
    }
    __syncthreads();

    // ===== Phase F: O = kScale*(gexp_i * OI + qkg @ C), store to gmem ======
    {
      const int i0 = ty * 4, c0 = tx * 4;
      u64 aO[4][2] = {};
      #pragma unroll 4
      for (int j = 0; j < Lc; j += 4) {
        u64 Bv[4][2];
        #pragma unroll
        for (int jj = 0; jj < 4; ++jj) ldBv(Bv[jj], &s.c[j + jj][c0]);
        float Af[4][4];
        #pragma unroll
        for (int r = 0; r < 4; ++r) LD4(&Af[r][0], &s.w[i0 + r][j]);
        mm4x4p(aO, Af, Bv);
      }
      const size_t obase = ((size_t)bh * Sc + (size_t)n * Lc) * DVc + (size_t)vb * DVB;
      #pragma unroll
      for (int r = 0; r < 4; ++r) {
        int i = i0 + r;
        float ge = s.gexp[i];
        float2 o0 = upk(aO[r][0]),   o1 = upk(aO[r][1]);
        float2 q0 = upk(accI[r][0]), q1 = upk(accI[r][1]);
        float4 o;
        o.x = kScale * (ge * q0.x + o0.x);
        o.y = kScale * (ge * q0.y + o0.y);
        o.z = kScale * (ge * q1.x + o1.x);
        o.w = kScale * (ge * q1.y + o1.y);
        *reinterpret_cast<float4*>(&out[obase + (size_t)i * DVc + c0]) = o;
      }
    }

    // ===== Phase G: S = S*exp(g_total) + (gexp*k)^T @ C ====================
    {
      const int d0 = (tid >> 4) * 8, c0 = (tid & 15) * 4;
      const float egt = s.gexp[Lc - 1];
      u64 acc[8][2] = {};
      #pragma unroll 2
      for (int i = 0; i < Lc; ++i) {
        u64 pge = pk2(s.gexp[i]);
        ulonglong2 cv = *reinterpret_cast<const ulonglong2*>(&s.c[i][c0]);
        u64 c0p = fmul2(pge, cv.x);
        u64 c1p = fmul2(pge, cv.y);
        float kf[8];
        LD4(&kf[0], &s.k[i][d0]);
        LD4(&kf[4], &s.k[i][d0 + 4]);
        #pragma unroll
        for (int r = 0; r < 8; ++r) {
          u64 pkr = pk2(kf[r]);
          acc[r][0] = ffma2(pkr, c0p, acc[r][0]);
          acc[r][1] = ffma2(pkr, c1p, acc[r][1]);
        }
      }
      #pragma unroll
      for (int r = 0; r < 8; ++r) {
        float2 f0 = upk(acc[r][0]), f1 = upk(acc[r][1]);
        float4 sv = *reinterpret_cast<float4*>(&s.S[d0 + r][c0]);
        sv.x = sv.x * egt + f0.x;
        sv.y = sv.y * egt + f0.y;
        sv.z = sv.z * egt + f1.x;
        sv.w = sv.w * egt + f1.y;
        *reinterpret_cast<float4*>(&s.S[d0 + r][c0]) = sv;
      }
    }
    __syncthreads();
  }  // chunk loop

  // Final state (second tuple element), if the output buffer includes it.
  if (out_elems >= OUT_ELEMS + STATE_ELEMS) {
    float* st = out + OUT_ELEMS + (size_t)bh * DKc * DVc + (size_t)vb * DVB;
    for (int f = tid; f < DKc * DVB / 4; f += NT) {
      int d = f >> 4, c4 = (f & 15) * 4;
      *reinterpret_cast<float4*>(&st[(size_t)d * DVc + c4]) =
          *reinterpret_cast<const float4*>(&s.S[d][c4]);
    }
  }
}

}  // namespace

extern "C" void kernel_launch(void* const* d_in, const int* in_sizes, int n_in,
                              void* d_out, int out_size) {
  (void)in_sizes; (void)n_in;
  const float* q  = (const float*)d_in[0];
  const float* k  = (const float*)d_in[1];
  const float* v  = (const float*)d_in[2];
  const float* g  = (const float*)d_in[3];
  const float* be = (const float*)d_in[4];

  cudaFuncSetAttribute(gdn_kernel, cudaFuncAttributeMaxDynamicSharedMemorySize,
                       (int)sizeof(Smem));

  dim3 grid(NBv, BHc);
  gdn_kernel<<<grid, NT, sizeof(Smem)>>>(q, k, v, g, be, (float*)d_out,
                                         (long long)out_size);
}

// round 6
// speedup vs baseline: 1.6013x; 1.0461x over previous
#include <cuda_runtime.h>
#include <cuda_bf16.h>
#include <math.h>

#define NT 256

namespace {

constexpr int Bc  = 2;
constexpr int Hc  = 16;
constexpr int Sc  = 4096;
constexpr int DKc = 128;
constexpr int DVc = 256;
constexpr int Lc  = 64;     // chunk length
constexpr int DVB = 64;     // Dv block per CTA
constexpr int BHc = Bc * Hc;          // 32
constexpr int NCH = Sc / Lc;          // 64 chunks
constexpr int NBv = DVc / DVB;        // 4 Dv blocks

constexpr float kScale = 0.08838834764831845f;   // 128^-0.5
constexpr long long OUT_ELEMS   = (long long)BHc * Sc * DVc;     // 33554432
constexpr long long STATE_ELEMS = (long long)BHc * DKc * DVc;    // 1048576

typedef unsigned long long u64;

struct Smem {
  float q[Lc][DKc];      // normalized q chunk
  float k[Lc][DKc];      // normalized k chunk
  float kt[DKc][Lc];     // k transposed
  float v[Lc][DVB];      // v slice; becomes R = gexp*(V - K@S) in place
  float a[Lc][Lc];       // A strict-lower gated (solve input)
  float w[Lc][Lc];       // qkg (gated causal q k^T)
  float t[Lc][Lc];       // T = A^-1 diag(beta)
  float c[Lc][DVB];      // solve scratch P, then correction C
  float S[DKc][DVB];     // running state slice
  float part[2][Lc][4];  // norm partial sums
  float ninv[2][Lc];
  float gcum[Lc];
  float gexp[Lc];
  float ginv[Lc];
  float beta[Lc];
};

#define LD4(dst, src) *reinterpret_cast<float4*>(dst) = *reinterpret_cast<const float4*>(src)

// ---- packed f32x2 helpers (Blackwell FFMA2 path, PTX-only) ----------------
__device__ __forceinline__ u64 pk2(float a) {
  u64 r; unsigned int ai = __float_as_uint(a);
  asm("mov.b64 %0, {%1, %1};" : "=l"(r) : "r"(ai));
  return r;
}
__device__ __forceinline__ u64 ffma2(u64 a, u64 b, u64 c) {
  u64 d;
  asm("fma.rn.f32x2 %0, %1, %2, %3;" : "=l"(d) : "l"(a), "l"(b), "l"(c));
  return d;
}
__device__ __forceinline__ u64 fmul2(u64 a, u64 b) {
  u64 d;
  asm("mul.rn.f32x2 %0, %1, %2;" : "=l"(d) : "l"(a), "l"(b));
  return d;
}
__device__ __forceinline__ float2 upk(u64 a) {
  unsigned int lo, hi;
  asm("mov.b64 {%0, %1}, %2;" : "=r"(lo), "=r"(hi) : "l"(a));
  return make_float2(__uint_as_float(lo), __uint_as_float(hi));
}

// acc[4 rows][2 col-pairs] += Af[4][4] (scalar) * Bv[4][2] (packed pairs)
__device__ __forceinline__ void mm4x4p(u64 acc[4][2], const float Af[4][4],
                                       const u64 Bv[4][2]) {
  #pragma unroll
  for (int r = 0; r < 4; ++r)
    #pragma unroll
    for (int kk = 0; kk < 4; ++kk) {
      u64 pa = pk2(Af[r][kk]);
      acc[r][0] = ffma2(pa, Bv[kk][0], acc[r][0]);
      acc[r][1] = ffma2(pa, Bv[kk][1], acc[r][1]);
    }
}

__device__ __forceinline__ void ldBv(u64 Bv2[2], const float* p) {
  ulonglong2 b = *reinterpret_cast<const ulonglong2*>(p);
  Bv2[0] = b.x; Bv2[1] = b.y;
}

__global__ void __launch_bounds__(NT, 1) gdn_kernel(
    const float* __restrict__ gq, const float* __restrict__ gk,
    const float* __restrict__ gv, const float* __restrict__ gg,
    const float* __restrict__ gb, float* __restrict__ out,
    long long out_elems)
{
  extern __shared__ char smem_raw[];
  Smem& s = *reinterpret_cast<Smem*>(smem_raw);

  const int tid = threadIdx.x;
  const int vb  = blockIdx.x;   // Dv block
  const int bh  = blockIdx.y;   // fused batch*head

  const size_t qkbase = (size_t)bh * Sc * DKc;
  const size_t vbase  = (size_t)bh * Sc * DVc + (size_t)vb * DVB;
  const size_t gbase  = (size_t)bh * Sc;

  for (int i = tid; i < DKc * DVB; i += NT) (&s.S[0][0])[i] = 0.f;
  __syncthreads();

  const int ty = tid >> 4;            // 0..15
  const int tx = tid & 15;            // 0..15
  const int ldrow = (tid * 32) >> 7;  // q/k load row (0..63)
  const int ldcol = (tid * 32) & 127; // q/k load col offset

  for (int n = 0; n < NCH; ++n) {
    // ================= Phase A: load + normalize q,k; load v,g,beta ========
    const float* qg = gq + qkbase + (size_t)n * Lc * DKc + tid * 32;
    const float* kg = gk + qkbase + (size_t)n * Lc * DKc + tid * 32;
    float4 bq[8], bk[8];
    float sq = 0.f, sk = 0.f;
    #pragma unroll
    for (int u = 0; u < 8; ++u) {
      float4 x = *reinterpret_cast<const float4*>(qg + u * 4);
      float4 y = *reinterpret_cast<const float4*>(kg + u * 4);
      bq[u] = x; bk[u] = y;
      sq += x.x * x.x + x.y * x.y + x.z * x.z + x.w * x.w;
      sk += y.x * y.x + y.y * y.y + y.z * y.z + y.w * y.w;
    }
    s.part[0][ldrow][ldcol >> 5] = sq;
    s.part[1][ldrow][ldcol >> 5] = sk;
    #pragma unroll
    for (int u = 0; u < 4; ++u) {
      int f = tid * 4 + u;
      int r = f >> 4, c4 = (f & 15) * 4;
      LD4(&s.v[r][c4], gv + vbase + (size_t)(n * Lc + r) * DVc + c4);
    }
    if (tid < Lc) {
      s.gcum[tid] = gg[gbase + n * Lc + tid];
      s.beta[tid] = gb[gbase + n * Lc + tid];
    }
    __syncthreads();

    if (tid < 2 * Lc) {
      int w = tid >> 6, r = tid & 63;
      float ssum = s.part[w][r][0] + s.part[w][r][1] + s.part[w][r][2] + s.part[w][r][3];
      s.ninv[w][r] = 1.f / (sqrtf(ssum) + 1e-6f);
    }
    if (tid == 128) {  // sequential cumsum over 64 gates (cheap)
      float acc = 0.f;
      for (int i = 0; i < Lc; ++i) { acc += s.gcum[i]; s.gcum[i] = acc; }
    }
    __syncthreads();

    if (tid < Lc) {
      float e = expf(s.gcum[tid]);
      s.gexp[tid] = e;
      s.ginv[tid] = 1.f / e;
    }
    {
      float iq = s.ninv[0][ldrow], ik = s.ninv[1][ldrow];
      #pragma unroll
      for (int u = 0; u < 8; ++u) {
        float4 x = bq[u];
        x.x *= iq; x.y *= iq; x.z *= iq; x.w *= iq;
        *reinterpret_cast<float4*>(&s.q[ldrow][ldcol + u * 4]) = x;
        float4 y = bk[u];
        y.x *= ik; y.y *= ik; y.z *= ik; y.w *= ik;
        *reinterpret_cast<float4*>(&s.k[ldrow][ldcol + u * 4]) = y;
        s.kt[ldcol + u * 4 + 0][ldrow] = y.x;
        s.kt[ldcol + u * 4 + 1][ldrow] = y.y;
        s.kt[ldcol + u * 4 + 2][ldrow] = y.z;
        s.kt[ldcol + u * 4 + 3][ldrow] = y.w;
      }
    }
    __syncthreads();

    // ===== Phase B (fused): A = k k^T and qkg = q k^T, sharing kt loads ====
    {
      const int i0 = ty * 4, j0 = tx * 4;
      u64 aA[4][2] = {}, aQ[4][2] = {};
      #pragma unroll 2
      for (int d = 0; d < DKc; d += 4) {
        u64 Bv[4][2];
        #pragma unroll
        for (int dd = 0; dd < 4; ++dd) ldBv(Bv[dd], &s.kt[d + dd][j0]);
        float Af[4][4];
        #pragma unroll
        for (int r = 0; r < 4; ++r) LD4(&Af[r][0], &s.k[i0 + r][d]);
        mm4x4p(aA, Af, Bv);
        #pragma unroll
        for (int r = 0; r < 4; ++r) LD4(&Af[r][0], &s.q[i0 + r][d]);
        mm4x4p(aQ, Af, Bv);
      }
      #pragma unroll
      for (int r = 0; r < 4; ++r) {
        int i = i0 + r;
        float bi = s.beta[i] * s.ginv[i];
        float gi = s.ginv[i];
        #pragma unroll
        for (int p = 0; p < 2; ++p) {
          float2 fa = upk(aA[r][p]);
          float2 fq = upk(aQ[r][p]);
          int j = j0 + 2 * p;
          s.a[i][j]     = (j     < i) ? bi * fa.x * s.gexp[j]     : 0.f;
          s.a[i][j + 1] = (j + 1 < i) ? bi * fa.y * s.gexp[j + 1] : 0.f;
          s.w[i][j]     = (j     <= i) ? fq.x * s.gexp[j]     * gi : 0.f;
          s.w[i][j + 1] = (j + 1 <= i) ? fq.y * s.gexp[j + 1] * gi : 0.f;
        }
      }
    }
    // no barrier: next phase touches only S/q/k/v; barrier before solve below

    // ===== Phase C (fused): R = gexp*(V - K@S) in s.v ; OI = Q@S in regs ===
    u64 accI[4][2] = {};   // persistent packed O_inter tile, consumed in F
    {
      const int r0 = ty * 4, c0 = tx * 4;
      u64 aK[4][2] = {};
      #pragma unroll 2
      for (int d = 0; d < DKc; d += 4) {
        u64 Bv[4][2];
        #pragma unroll
        for (int dd = 0; dd < 4; ++dd) ldBv(Bv[dd], &s.S[d + dd][c0]);
        float Af[4][4];
        #pragma unroll
        for (int r = 0; r < 4; ++r) LD4(&Af[r][0], &s.k[r0 + r][d]);
        mm4x4p(aK, Af, Bv);
        #pragma unroll
        for (int r = 0; r < 4; ++r) LD4(&Af[r][0], &s.q[r0 + r][d]);
        mm4x4p(accI, Af, Bv);
      }
      #pragma unroll
      for (int r = 0; r < 4; ++r) {
        float ge = s.gexp[r0 + r];
        float2 f0 = upk(aK[r][0]), f1 = upk(aK[r][1]);
        float4 vv = *reinterpret_cast<float4*>(&s.v[r0 + r][c0]);
        vv.x = ge * (vv.x - f0.x);
        vv.y = ge * (vv.y - f0.y);
        vv.z = ge * (vv.z - f1.x);
        vv.w = ge * (vv.w - f1.y);
        *reinterpret_cast<float4*>(&s.v[r0 + r][c0]) = vv;
      }
    }
    __syncthreads();   // s.a/s.w complete, s.v(R) complete

    // ===== Phase D: blocked forward substitution, T = A^-1 diag(beta) ======
    // Block 0: rows 0..31. 4 independent accumulators break the serial FMA
    // chain: critical path per row ~12cyc instead of ~4*i.
    if (tid < Lc) {
      float tc[32];
      #pragma unroll
      for (int i = 0; i < 32; ++i) {
        float v0 = (tid == i) ? s.beta[i] : 0.f;
        float v1 = 0.f, v2 = 0.f, v3 = 0.f;
        int j = 0;
        #pragma unroll
        for (; j + 4 <= i; j += 4) {
          v0 -= s.a[i][j + 0] * tc[j + 0];
          v1 -= s.a[i][j + 1] * tc[j + 1];
          v2 -= s.a[i][j + 2] * tc[j + 2];
          v3 -= s.a[i][j + 3] * tc[j + 3];
        }
        #pragma unroll
        for (; j < i; ++j) v0 -= s.a[i][j] * tc[j];
        float val = (v0 + v1) + (v2 + v3);
        tc[i] = val;
        s.t[i][tid] = val;
      }
    }
    __syncthreads();
    // Off-diagonal: P[32][64] = A[32:64][0:32] @ T[0:32][:]  (all 256 threads)
    {
      const int rp0 = (tid >> 5) * 4;   // 0..28
      const int cp0 = (tid & 31) * 2;   // 0..62
      float accP[4][2] = {};
      #pragma unroll
      for (int j = 0; j < 32; j += 4) {
        float Bf[4][2];
        #pragma unroll
        for (int jj = 0; jj < 4; ++jj) {
          float2 t2 = *reinterpret_cast<const float2*>(&s.t[j + jj][cp0]);
          Bf[jj][0] = t2.x; Bf[jj][1] = t2.y;
        }
        #pragma unroll
        for (int r = 0; r < 4; ++r) {
          float4 av = *reinterpret_cast<const float4*>(&s.a[32 + rp0 + r][j]);
          accP[r][0] += av.x * Bf[0][0] + av.y * Bf[1][0] + av.z * Bf[2][0] + av.w * Bf[3][0];
          accP[r][1] += av.x * Bf[0][1] + av.y * Bf[1][1] + av.z * Bf[2][1] + av.w * Bf[3][1];
        }
      }
      #pragma unroll
      for (int r = 0; r < 4; ++r) {
        s.c[rp0 + r][cp0]     = accP[r][0];
        s.c[rp0 + r][cp0 + 1] = accP[r][1];
      }
    }
    __syncthreads();
    // Block 1: rows 32..63 (same 4-accumulator ILP scheme)
    if (tid < Lc) {
      float tc[32];
      #pragma unroll
      for (int i = 0; i < 32; ++i) {
        int gi = 32 + i;
        float v0 = ((tid == gi) ? s.beta[gi] : 0.f) - s.c[i][tid];
        float v1 = 0.f, v2 = 0.f, v3 = 0.f;
        int j = 0;
        #pragma unroll
        for (; j + 4 <= i; j += 4) {
          v0 -= s.a[gi][32 + j + 0] * tc[j + 0];
          v1 -= s.a[gi][32 + j + 1] * tc[j + 1];
          v2 -= s.a[gi][32 + j + 2] * tc[j + 2];
          v3 -= s.a[gi][32 + j + 3] * tc[j + 3];
        }
        #pragma unroll
        for (; j < i; ++j) v0 -= s.a[gi][32 + j] * tc[j];
        float val = (v0 + v1) + (v2 + v3);
        tc[i] = val;
        s.t[gi][tid] = val;
      }
    }
    __syncthreads();

    // ===== Phase E: C = T @ R  (triangular: T[i][j]=0 for j>i) =============
    {
      const int i0 = ty * 4, c0 = tx * 4;
      u64 aC[4][2] = {};
      #pragma unroll 2
      for (int j = 0; j <= i0; j += 4) {   // last block covers j=i0..i0+3
        u64 Bv[4][2];
        #pragma unroll
        for (int jj = 0; jj < 4; ++jj) ldBv(Bv[jj], &s.v[j + jj][c0]);
        float Af[4][4];
        #pragma unroll
        for (int r = 0; r < 4; ++r) LD4(&Af[r][0], &s.t[i0 + r][j]);
        mm4x4p(aC, Af, Bv);
      }
      #pragma unroll
      for (int r = 0; r < 4; ++r) {
        float2 f0 = upk(aC[r][0]), f1 = upk(aC[r][1]);
        *reinterpret_cast<float4*>(&s.c[i0 + r][c0]) =
            make_float4(f0.x, f0.y, f1.x, f1.y);
      }
    }
    __syncthreads();

    // ===== Phase F: O = kScale*(gexp_i * OI + qkg @ C), store to gmem ======
    // qkg (s.w) is causal-lower: truncate j at the diagonal tile.
    {
      const int i0 = ty * 4, c0 = tx * 4;
      u64 aO[4][2] = {};
      #pragma unroll 2
      for (int j = 0; j <= i0; j += 4) {
        u64 Bv[4][2];
        #pragma unroll
        for (int jj = 0; jj < 4; ++jj) ldBv(Bv[jj], &s.c[j + jj][c0]);
        float Af[4][4];
        #pragma unroll
        for (int r = 0; r < 4; ++r) LD4(&Af[r][0], &s.w[i0 + r][j]);
        mm4x4p(aO, Af, Bv);
      }
      const size_t obase = ((size_t)bh * Sc + (size_t)n * Lc) * DVc + (size_t)vb * DVB;
      #pragma unroll
      for (int r = 0; r < 4; ++r) {
        int i = i0 + r;
        float ge = s.gexp[i];
        float2 o0 = upk(aO[r][0]),   o1 = upk(aO[r][1]);
        float2 q0 = upk(accI[r][0]), q1 = upk(accI[r][1]);
        float4 o;
        o.x = kScale * (ge * q0.x + o0.x);
        o.y = kScale * (ge * q0.y + o0.y);
        o.z = kScale * (ge * q1.x + o1.x);
        o.w = kScale * (ge * q1.y + o1.y);
        *reinterpret_cast<float4*>(&out[obase + (size_t)i * DVc + c0]) = o;
      }
    }

    // ===== Phase G: S = S*exp(g_total) + (gexp*k)^T @ C ====================
    {
      const int d0 = (tid >> 4) * 8, c0 = (tid & 15) * 4;
      const float egt = s.gexp[Lc - 1];
      u64 acc[8][2] = {};
      #pragma unroll 2
      for (int i = 0; i < Lc; ++i) {
        u64 pge = pk2(s.gexp[i]);
        ulonglong2 cv = *reinterpret_cast<const ulonglong2*>(&s.c[i][c0]);
        u64 c0p = fmul2(pge, cv.x);
        u64 c1p = fmul2(pge, cv.y);
        float kf[8];
        LD4(&kf[0], &s.k[i][d0]);
        LD4(&kf[4], &s.k[i][d0 + 4]);
        #pragma unroll
        for (int r = 0; r < 8; ++r) {
          u64 pkr = pk2(kf[r]);
          acc[r][0] = ffma2(pkr, c0p, acc[r][0]);
          acc[r][1] = ffma2(pkr, c1p, acc[r][1]);
        }
      }
      #pragma unroll
      for (int r = 0; r < 8; ++r) {
        float2 f0 = upk(acc[r][0]), f1 = upk(acc[r][1]);
        float4 sv = *reinterpret_cast<float4*>(&s.S[d0 + r][c0]);
        sv.x = sv.x * egt + f0.x;
        sv.y = sv.y * egt + f0.y;
        sv.z = sv.z * egt + f1.x;
        sv.w = sv.w * egt + f1.y;
        *reinterpret_cast<float4*>(&s.S[d0 + r][c0]) = sv;
      }
    }
    __syncthreads();
  }  // chunk loop

  // Final state (second tuple element), if the output buffer includes it.
  if (out_elems >= OUT_ELEMS + STATE_ELEMS) {
    float* st = out + OUT_ELEMS + (size_t)bh * DKc * DVc + (size_t)vb * DVB;
    for (int f = tid; f < DKc * DVB / 4; f += NT) {
      int d = f >> 4, c4 = (f & 15) * 4;
      *reinterpret_cast<float4*>(&st[(size_t)d * DVc + c4]) =
          *reinterpret_cast<const float4*>(&s.S[d][c4]);
    }
  }
}

}  // namespace

extern "C" void kernel_launch(void* const* d_in, const int* in_sizes, int n_in,
                              void* d_out, int out_size) {
  (void)in_sizes; (void)n_in;
  const float* q  = (const float*)d_in[0];
  const float* k  = (const float*)d_in[1];
  const float* v  = (const float*)d_in[2];
  const float* g  = (const float*)d_in[3];
  const float* be = (const float*)d_in[4];

  cudaFuncSetAttribute(gdn_kernel, cudaFuncAttributeMaxDynamicSharedMemorySize,
                       (int)sizeof(Smem));

  dim3 grid(NBv, BHc);
  gdn_kernel<<<grid, NT, sizeof(Smem)>>>(q, k, v, g, be, (float*)d_out,
                                         (long long)out_size);
}

// round 7
// speedup vs baseline: 1.6677x; 1.0415x over previous
#include <cuda_runtime.h>
#include <cuda_bf16.h>
#include <math.h>

#define NT 256

namespace {

constexpr int Bc  = 2;
constexpr int Hc  = 16;
constexpr int Sc  = 4096;
constexpr int DKc = 128;
constexpr int DVc = 256;
constexpr int Lc  = 64;     // chunk length
constexpr int DVB = 64;     // Dv block per CTA
constexpr int BHc = Bc * Hc;          // 32
constexpr int NCH = Sc / Lc;          // 64 chunks
constexpr int NBv = DVc / DVB;        // 4 Dv blocks

constexpr float kScale = 0.08838834764831845f;   // 128^-0.5
constexpr long long OUT_ELEMS   = (long long)BHc * Sc * DVc;     // 33554432
constexpr long long STATE_ELEMS = (long long)BHc * DKc * DVc;    // 1048576

typedef unsigned long long u64;

// Row swizzle for d-indexed rows (q/k/St): XOR bits [2:5) of the float column
// index by (row>>2)&7. Preserves 16B (LD4) alignment; spreads the 8 threads of
// an LDS phase (reading 8 different rows at the same d) over 8 bank groups.
__device__ __host__ __forceinline__ int SWZ(int row, int d) {
  return d ^ (((row >> 2) & 7) << 2);
}

struct Smem {
  float q[Lc][DKc];      // normalized q chunk (row-swizzled)
  float k[Lc][DKc];      // normalized k chunk (row-swizzled)
  float v[Lc][DVB];      // v slice; becomes R = gexp*(V - K@S) in place
  float a[Lc][Lc];       // A strict-lower gated (solve input)
  float w[Lc][Lc];       // qkg (gated causal q k^T)
  float t[Lc][Lc];       // T = A^-1 diag(beta)
  float c[Lc][DVB];      // solve scratch P, then correction C
  float St[DVB][DKc];    // running state slice, TRANSPOSED (row-swizzled)
  float part[2][Lc][4];  // norm partial sums
  float ninv[2][Lc];
  float gcum[Lc];
  float gexp[Lc];
  float ginv[Lc];
  float beta[Lc];
};

#define LD4(dst, src) *reinterpret_cast<float4*>(dst) = *reinterpret_cast<const float4*>(src)

// ---- packed f32x2 helpers (Blackwell FFMA2 path, PTX-only) ----------------
__device__ __forceinline__ u64 pk2(float a) {
  u64 r; unsigned int ai = __float_as_uint(a);
  asm("mov.b64 %0, {%1, %1};" : "=l"(r) : "r"(ai));
  return r;
}
__device__ __forceinline__ u64 ffma2(u64 a, u64 b, u64 c) {
  u64 d;
  asm("fma.rn.f32x2 %0, %1, %2, %3;" : "=l"(d) : "l"(a), "l"(b), "l"(c));
  return d;
}
__device__ __forceinline__ float2 upk(u64 a) {
  unsigned int lo, hi;
  asm("mov.b64 {%0, %1}, %2;" : "=r"(lo), "=r"(hi) : "l"(a));
  return make_float2(__uint_as_float(lo), __uint_as_float(hi));
}
__device__ __forceinline__ float foldp(u64 a) {  // sum even/odd-d partials
  float2 f = upk(a);
  return f.x + f.y;
}
// load 16B (4 floats = 2 d-pairs) as two u64 lanes
__device__ __forceinline__ void ld2p(u64 p[2], const float* addr) {
  ulonglong2 t = *reinterpret_cast<const ulonglong2*>(addr);
  p[0] = t.x; p[1] = t.y;
}

// (kept for phases E/F which stay in broadcast-A form)
__device__ __forceinline__ void mm4x4p(u64 acc[4][2], const float Af[4][4],
                                       const u64 Bv[4][2]) {
  #pragma unroll
  for (int r = 0; r < 4; ++r)
    #pragma unroll
    for (int kk = 0; kk < 4; ++kk) {
      u64 pa = pk2(Af[r][kk]);
      acc[r][0] = ffma2(pa, Bv[kk][0], acc[r][0]);
      acc[r][1] = ffma2(pa, Bv[kk][1], acc[r][1]);
    }
}
__device__ __forceinline__ void ldBv(u64 Bv2[2], const float* p) {
  ulonglong2 b = *reinterpret_cast<const ulonglong2*>(p);
  Bv2[0] = b.x; Bv2[1] = b.y;
}

__global__ void __launch_bounds__(NT, 1) gdn_kernel(
    const float* __restrict__ gq, const float* __restrict__ gk,
    const float* __restrict__ gv, const float* __restrict__ gg,
    const float* __restrict__ gb, float* __restrict__ out,
    long long out_elems)
{
  extern __shared__ char smem_raw[];
  Smem& s = *reinterpret_cast<Smem*>(smem_raw);

  const int tid = threadIdx.x;
  const int vb  = blockIdx.x;   // Dv block
  const int bh  = blockIdx.y;   // fused batch*head

  const size_t qkbase = (size_t)bh * Sc * DKc;
  const size_t vbase  = (size_t)bh * Sc * DVc + (size_t)vb * DVB;
  const size_t gbase  = (size_t)bh * Sc;

  for (int i = tid; i < DKc * DVB; i += NT) (&s.St[0][0])[i] = 0.f;
  __syncthreads();

  const int ty = tid >> 4;            // 0..15
  const int tx = tid & 15;            // 0..15
  const int ldrow = (tid * 32) >> 7;  // q/k load row (0..63)
  const int ldcol = (tid * 32) & 127; // q/k load col offset

  for (int n = 0; n < NCH; ++n) {
    // ================= Phase A: load + normalize q,k; load v,g,beta ========
    const float* qg = gq + qkbase + (size_t)n * Lc * DKc + tid * 32;
    const float* kg = gk + qkbase + (size_t)n * Lc * DKc + tid * 32;
    float4 bq[8], bk[8];
    float sq = 0.f, sk = 0.f;
    #pragma unroll
    for (int u = 0; u < 8; ++u) {
      float4 x = *reinterpret_cast<const float4*>(qg + u * 4);
      float4 y = *reinterpret_cast<const float4*>(kg + u * 4);
      bq[u] = x; bk[u] = y;
      sq += x.x * x.x + x.y * x.y + x.z * x.z + x.w * x.w;
      sk += y.x * y.x + y.y * y.y + y.z * y.z + y.w * y.w;
    }
    s.part[0][ldrow][ldcol >> 5] = sq;
    s.part[1][ldrow][ldcol >> 5] = sk;
    #pragma unroll
    for (int u = 0; u < 4; ++u) {
      int f = tid * 4 + u;
      int r = f >> 4, c4 = (f & 15) * 4;
      LD4(&s.v[r][c4], gv + vbase + (size_t)(n * Lc + r) * DVc + c4);
    }
    if (tid < Lc) {
      s.gcum[tid] = gg[gbase + n * Lc + tid];
      s.beta[tid] = gb[gbase + n * Lc + tid];
    }
    __syncthreads();

    if (tid < 2 * Lc) {
      int w = tid >> 6, r = tid & 63;
      float ssum = s.part[w][r][0] + s.part[w][r][1] + s.part[w][r][2] + s.part[w][r][3];
      s.ninv[w][r] = 1.f / (sqrtf(ssum) + 1e-6f);
    }
    if (tid == 128) {  // sequential cumsum over 64 gates (cheap)
      float acc = 0.f;
      for (int i = 0; i < Lc; ++i) { acc += s.gcum[i]; s.gcum[i] = acc; }
    }
    __syncthreads();

    if (tid < Lc) {
      float e = expf(s.gcum[tid]);
      s.gexp[tid] = e;
      s.ginv[tid] = 1.f / e;
    }
    {
      float iq = s.ninv[0][ldrow], ik = s.ninv[1][ldrow];
      const int swr = ((ldrow >> 2) & 7) << 2;
      #pragma unroll
      for (int u = 0; u < 8; ++u) {
        int cc = (ldcol + u * 4) ^ swr;   // 16B-aligned swizzled column
        float4 x = bq[u];
        x.x *= iq; x.y *= iq; x.z *= iq; x.w *= iq;
        *reinterpret_cast<float4*>(&s.q[ldrow][cc]) = x;
        float4 y = bk[u];
        y.x *= ik; y.y *= ik; y.z *= ik; y.w *= ik;
        *reinterpret_cast<float4*>(&s.k[ldrow][cc]) = y;
      }
    }
    __syncthreads();

    // ===== Phase B (fused, d-pair packed): A = k k^T and qkg = q k^T =======
    // Both operands are natural row loads; accumulators hold even/odd-d
    // partial pairs; zero broadcast movs.
    {
      const int i0 = ty * 4, j0 = tx * 4;
      const int sA = (ty & 7) << 2, sB = (tx & 7) << 2;
      u64 aA[4][4] = {}, aQ[4][4] = {};
      #pragma unroll 2
      for (int d = 0; d < DKc; d += 4) {
        u64 Bp[4][2];
        #pragma unroll
        for (int cc = 0; cc < 4; ++cc) ld2p(Bp[cc], &s.k[j0 + cc][d ^ sB]);
        #pragma unroll
        for (int r = 0; r < 4; ++r) {
          u64 Ap[2];
          ld2p(Ap, &s.k[i0 + r][d ^ sA]);
          #pragma unroll
          for (int cc = 0; cc < 4; ++cc) {
            aA[r][cc] = ffma2(Ap[0], Bp[cc][0], aA[r][cc]);
            aA[r][cc] = ffma2(Ap[1], Bp[cc][1], aA[r][cc]);
          }
          ld2p(Ap, &s.q[i0 + r][d ^ sA]);
          #pragma unroll
          for (int cc = 0; cc < 4; ++cc) {
            aQ[r][cc] = ffma2(Ap[0], Bp[cc][0], aQ[r][cc]);
            aQ[r][cc] = ffma2(Ap[1], Bp[cc][1], aQ[r][cc]);
          }
        }
      }
      #pragma unroll
      for (int r = 0; r < 4; ++r) {
        int i = i0 + r;
        float bi = s.beta[i] * s.ginv[i];
        float gi = s.ginv[i];
        #pragma unroll
        for (int cc = 0; cc < 4; ++cc) {
          int j = j0 + cc;
          float fa = foldp(aA[r][cc]);
          float fq = foldp(aQ[r][cc]);
          s.a[i][j] = (j <  i) ? bi * fa * s.gexp[j]      : 0.f;
          s.w[i][j] = (j <= i) ? fq * s.gexp[j] * gi      : 0.f;
        }
      }
    }
    // no barrier: next phase touches only St/q/k/v; barrier before solve below

    // ===== Phase C (fused, d-pair packed): R = gexp*(V - K@St^T) in s.v ;
    //       O_inter = Q@St^T folded into qI registers ========================
    float qI[4][4];   // persistent O_inter tile, consumed in F
    {
      const int r0 = ty * 4, c0 = tx * 4;
      const int sA = (ty & 7) << 2, sB = (tx & 7) << 2;
      u64 aK[4][4] = {}, aI[4][4] = {};
      #pragma unroll 2
      for (int d = 0; d < DKc; d += 4) {
        u64 Bp[4][2];
        #pragma unroll
        for (int cc = 0; cc < 4; ++cc) ld2p(Bp[cc], &s.St[c0 + cc][d ^ sB]);
        #pragma unroll
        for (int r = 0; r < 4; ++r) {
          u64 Ap[2];
          ld2p(Ap, &s.k[r0 + r][d ^ sA]);
          #pragma unroll
          for (int cc = 0; cc < 4; ++cc) {
            aK[r][cc] = ffma2(Ap[0], Bp[cc][0], aK[r][cc]);
            aK[r][cc] = ffma2(Ap[1], Bp[cc][1], aK[r][cc]);
          }
          ld2p(Ap, &s.q[r0 + r][d ^ sA]);
          #pragma unroll
          for (int cc = 0; cc < 4; ++cc) {
            aI[r][cc] = ffma2(Ap[0], Bp[cc][0], aI[r][cc]);
            aI[r][cc] = ffma2(Ap[1], Bp[cc][1], aI[r][cc]);
          }
        }
      }
      #pragma unroll
      for (int r = 0; r < 4; ++r) {
        float ge = s.gexp[r0 + r];
        float4 vv = *reinterpret_cast<float4*>(&s.v[r0 + r][c0]);
        vv.x = ge * (vv.x - foldp(aK[r][0]));
        vv.y = ge * (vv.y - foldp(aK[r][1]));
        vv.z = ge * (vv.z - foldp(aK[r][2]));
        vv.w = ge * (vv.w - foldp(aK[r][3]));
        *reinterpret_cast<float4*>(&s.v[r0 + r][c0]) = vv;
        #pragma unroll
        for (int cc = 0; cc < 4; ++cc) qI[r][cc] = foldp(aI[r][cc]);
      }
    }
    __syncthreads();   // s.a/s.w complete, s.v(R) complete

    // ===== Phase D: blocked forward substitution, T = A^-1 diag(beta) ======
    if (tid < Lc) {
      float tc[32];
      #pragma unroll
      for (int i = 0; i < 32; ++i) {
        float v0 = (tid == i) ? s.beta[i] : 0.f;
        float v1 = 0.f, v2 = 0.f, v3 = 0.f;
        int j = 0;
        #pragma unroll
        for (; j + 4 <= i; j += 4) {
          v0 -= s.a[i][j + 0] * tc[j + 0];
          v1 -= s.a[i][j + 1] * tc[j + 1];
          v2 -= s.a[i][j + 2] * tc[j + 2];
          v3 -= s.a[i][j + 3] * tc[j + 3];
        }
        #pragma unroll
        for (; j < i; ++j) v0 -= s.a[i][j] * tc[j];
        float val = (v0 + v1) + (v2 + v3);
        tc[i] = val;
        s.t[i][tid] = val;
      }
    }
    __syncthreads();
    // Off-diagonal: P[32][64] = A[32:64][0:32] @ T[0:32][:]  (all 256 threads)
    {
      const int rp0 = (tid >> 5) * 4;   // 0..28
      const int cp0 = (tid & 31) * 2;   // 0..62
      float accP[4][2] = {};
      #pragma unroll
      for (int j = 0; j < 32; j += 4) {
        float Bf[4][2];
        #pragma unroll
        for (int jj = 0; jj < 4; ++jj) {
          float2 t2 = *reinterpret_cast<const float2*>(&s.t[j + jj][cp0]);
          Bf[jj][0] = t2.x; Bf[jj][1] = t2.y;
        }
        #pragma unroll
        for (int r = 0; r < 4; ++r) {
          float4 av = *reinterpret_cast<const float4*>(&s.a[32 + rp0 + r][j]);
          accP[r][0] += av.x * Bf[0][0] + av.y * Bf[1][0] + av.z * Bf[2][0] + av.w * Bf[3][0];
          accP[r][1] += av.x * Bf[0][1] + av.y * Bf[1][1] + av.z * Bf[2][1] + av.w * Bf[3][1];
        }
      }
      #pragma unroll
      for (int r = 0; r < 4; ++r) {
        s.c[rp0 + r][cp0]     = accP[r][0];
        s.c[rp0 + r][cp0 + 1] = accP[r][1];
      }
    }
    __syncthreads();
    // Block 1: rows 32..63 (4-accumulator ILP)
    if (tid < Lc) {
      float tc[32];
      #pragma unroll
      for (int i = 0; i < 32; ++i) {
        int gi = 32 + i;
        float v0 = ((tid == gi) ? s.beta[gi] : 0.f) - s.c[i][tid];
        float v1 = 0.f, v2 = 0.f, v3 = 0.f;
        int j = 0;
        #pragma unroll
        for (; j + 4 <= i; j += 4) {
          v0 -= s.a[gi][32 + j + 0] * tc[j + 0];
          v1 -= s.a[gi][32 + j + 1] * tc[j + 1];
          v2 -= s.a[gi][32 + j + 2] * tc[j + 2];
          v3 -= s.a[gi][32 + j + 3] * tc[j + 3];
        }
        #pragma unroll
        for (; j < i; ++j) v0 -= s.a[gi][32 + j] * tc[j];
        float val = (v0 + v1) + (v2 + v3);
        tc[i] = val;
        s.t[gi][tid] = val;
      }
    }
    __syncthreads();

    // ===== Phase E: C = T @ R  (triangular: T[i][j]=0 for j>i) =============
    {
      const int i0 = ty * 4, c0 = tx * 4;
      u64 aC[4][2] = {};
      #pragma unroll 2
      for (int j = 0; j <= i0; j += 4) {   // last block covers j=i0..i0+3
        u64 Bv[4][2];
        #pragma unroll
        for (int jj = 0; jj < 4; ++jj) ldBv(Bv[jj], &s.v[j + jj][c0]);
        float Af[4][4];
        #pragma unroll
        for (int r = 0; r < 4; ++r) LD4(&Af[r][0], &s.t[i0 + r][j]);
        mm4x4p(aC, Af, Bv);
      }
      #pragma unroll
      for (int r = 0; r < 4; ++r) {
        float2 f0 = upk(aC[r][0]), f1 = upk(aC[r][1]);
        *reinterpret_cast<float4*>(&s.c[i0 + r][c0]) =
            make_float4(f0.x, f0.y, f1.x, f1.y);
      }
    }
    __syncthreads();

    // ===== Phase F: O = kScale*(gexp_i * qI + qkg @ C), store to gmem ======
    {
      const int i0 = ty * 4, c0 = tx * 4;
      u64 aO[4][2] = {};
      #pragma unroll 2
      for (int j = 0; j <= i0; j += 4) {
        u64 Bv[4][2];
        #pragma unroll
        for (int jj = 0; jj < 4; ++jj) ldBv(Bv[jj], &s.c[j + jj][c0]);
        float Af[4][4];
        #pragma unroll
        for (int r = 0; r < 4; ++r) LD4(&Af[r][0], &s.w[i0 + r][j]);
        mm4x4p(aO, Af, Bv);
      }
      const size_t obase = ((size_t)bh * Sc + (size_t)n * Lc) * DVc + (size_t)vb * DVB;
      #pragma unroll
      for (int r = 0; r < 4; ++r) {
        int i = i0 + r;
        float ge = s.gexp[i];
        float2 o0 = upk(aO[r][0]), o1 = upk(aO[r][1]);
        float4 o;
        o.x = kScale * (ge * qI[r][0] + o0.x);
        o.y = kScale * (ge * qI[r][1] + o0.y);
        o.z = kScale * (ge * qI[r][2] + o1.x);
        o.w = kScale * (ge * qI[r][3] + o1.y);
        *reinterpret_cast<float4*>(&out[obase + (size_t)i * DVc + c0]) = o;
      }
    }

    // ===== Phase G: St[c][d] = egt*St[c][d] + sum_i (gexp_i C[i][c]) k[i][d]
    {
      const int c0 = (tid & 15) * 4;
      const int d0 = (tid >> 4) * 8;
      const int sc = ((tid & 15) & 7) << 2;  // swizzle for St rows c0..c0+3
      const float egt = s.gexp[Lc - 1];
      const u64 egt2 = pk2(egt);
      u64 acc[4][4] = {};
      #pragma unroll 2
      for (int i = 0; i < Lc; ++i) {
        const int si = ((i >> 2) & 7) << 2;
        u64 kp[4];
        ld2p(kp,     &s.k[i][d0 ^ si]);
        ld2p(kp + 2, &s.k[i][(d0 + 4) ^ si]);
        float4 cv = *reinterpret_cast<const float4*>(&s.c[i][c0]);
        float ge = s.gexp[i];
        u64 gc0 = pk2(ge * cv.x), gc1 = pk2(ge * cv.y);
        u64 gc2 = pk2(ge * cv.z), gc3 = pk2(ge * cv.w);
        #pragma unroll
        for (int dp = 0; dp < 4; ++dp) {
          acc[0][dp] = ffma2(gc0, kp[dp], acc[0][dp]);
          acc[1][dp] = ffma2(gc1, kp[dp], acc[1][dp]);
          acc[2][dp] = ffma2(gc2, kp[dp], acc[2][dp]);
          acc[3][dp] = ffma2(gc3, kp[dp], acc[3][dp]);
        }
      }
      #pragma unroll
      for (int cc = 0; cc < 4; ++cc) {
        float* row = &s.St[c0 + cc][0];
        u64* p0 = reinterpret_cast<u64*>(row + (d0 ^ sc));
        u64* p1 = reinterpret_cast<u64*>(row + ((d0 + 4) ^ sc));
        p0[0] = ffma2(p0[0], egt2, acc[cc][0]);
        p0[1] = ffma2(p0[1], egt2, acc[cc][1]);
        p1[0] = ffma2(p1[0], egt2, acc[cc][2]);
        p1[1] = ffma2(p1[1], egt2, acc[cc][3]);
      }
    }
    __syncthreads();
  }  // chunk loop

  // Final state (second tuple element), if the output buffer includes it.
  if (out_elems >= OUT_ELEMS + STATE_ELEMS) {
    float* st = out + OUT_ELEMS + (size_t)bh * DKc * DVc + (size_t)vb * DVB;
    for (int f = tid; f < DKc * DVB; f += NT) {
      int d = f >> 6;        // 0..127
      int c = f & 63;        // 0..63 (contiguous for coalescing)
      st[(size_t)d * DVc + c] = s.St[c][SWZ(c, d)];
    }
  }
}

}  // namespace

extern "C" void kernel_launch(void* const* d_in, const int* in_sizes, int n_in,
                              void* d_out, int out_size) {
  (void)in_sizes; (void)n_in;
  const float* q  = (const float*)d_in[0];
  const float* k  = (const float*)d_in[1];
  const float* v  = (const float*)d_in[2];
  const float* g  = (const float*)d_in[3];
  const float* be = (const float*)d_in[4];

  cudaFuncSetAttribute(gdn_kernel, cudaFuncAttributeMaxDynamicSharedMemorySize,
                       (int)sizeof(Smem));

  dim3 grid(NBv, BHc);
  gdn_kernel<<<grid, NT, sizeof(Smem)>>>(q, k, v, g, be, (float*)d_out,
                                         (long long)out_size);
}